// round 9
// baseline (speedup 1.0000x reference)
#include <cuda_runtime.h>
#include <cuda_fp16.h>
#include <math.h>
#include <stdint.h>

// Problem constants
#define B_ 1024
#define I_ 256
#define O_ 256
#define K_ 128

// Tiling (R5/R8 measured-best config)
#define OT 32          // outputs per CTA (lane = o)
#define BT 256         // batches per CTA
#define NSEG 16        // i-segments (grid.z)
#define ISEG (I_ / NSEG)
#define NW 16          // warps per CTA (512 threads)
#define BPW (BT / NW)  // 16 batches per warp
#define RS 129         // row stride in uint32 words; odd -> gather bank (lane+l)%32 conflict-free

// Per-(b,i) packed activation data [i][b], 8 bytes:
//  .x = half2(silu(tanh(x)), frac)   .y = l*4 (byte offset into pair row)
__device__ uint2 g_pk8[I_ * B_];
// Exclusive partial sums per i-segment (deterministic)
__device__ float g_part[NSEG][B_][O_];

__global__ __launch_bounds__(256) void prep_kernel(const float* __restrict__ x) {
    int idx = blockIdx.x * 256 + threadIdx.x;   // i-major: coalesced g_pk8 writes
    int i = idx / B_;
    int b = idx % B_;
    float xv = __ldg(&x[b * I_ + i]);           // strided read; 1MB tensor, L2-resident
    float ax = fabsf(xv);
    float e  = __expf(-2.0f * ax);
    float r  = (1.0f - e) / (1.0f + e);
    float p  = copysignf(r, xv);                 // tanh(x) in [-1,1] => clip identity
    float sg = 1.0f / (1.0f + __expf(-p));
    float act = p * sg;                           // silu(p)
    float scaled = fminf(fmaxf((p + 1.0f) * 63.5f, 0.0f), 127.0f);
    int   l    = (int)scaled;                     // 0..127
    float frac = scaled - (float)l;
    __half2 h = __floats2half2_rn(act, frac);
    uint2 v;
    v.x = *reinterpret_cast<unsigned int*>(&h);
    v.y = (unsigned int)(l * 4);
    g_pk8[idx] = v;
}

__global__ __launch_bounds__(512, 2) void kan_main(
    const float* __restrict__ bw,     // [O, I]
    const float* __restrict__ coeff,  // [O, I, K]
    const float* __restrict__ scale)  // [O, I]
{
    __shared__ unsigned int sC[2][OT * RS];       // 2 x 16.5 KB: fp16 pair rows (pad word unread)
    __shared__ __align__(16) uint2 sPk[2][BT];    // 2 x 2 KB
    __shared__ float sW[ISEG][OT];                // 2 KB base weights for the segment

    const int tid  = threadIdx.x;
    const int lane = tid & 31;
    const int warp = tid >> 5;
    const int o0 = blockIdx.x * OT;
    const int b0 = blockIdx.y * BT;
    const int i0 = blockIdx.z * ISEG;
    const int r0 = warp * 2;
    const int r1 = warp * 2 + 1;

    // One-time preload of base-weight slice
    for (int t = tid; t < ISEG * OT; t += 512) {
        int oo = t >> 4, ii = t & 15;
        sW[ii][oo] = bw[(size_t)(o0 + oo) * I_ + i0 + ii];
    }

    float acc[BPW];
#pragma unroll
    for (int j = 0; j < BPW; j++) acc[j] = 0.0f;

    // Register prefetch buffers: left taps a*, right taps b* (k+1 wrapped; safe since l=127 => frac=0)
    float a0[4], b0v[4], a1[4], b1v[4], sc0, sc1;
    uint2 pkr;

    // Prologue: fetch iteration 0
    {
        const float* s0 = coeff + ((size_t)(o0 + r0) * I_ + i0) * (size_t)K_;
        const float* s1 = coeff + ((size_t)(o0 + r1) * I_ + i0) * (size_t)K_;
#pragma unroll
        for (int j = 0; j < 4; j++) {
            int k = lane + 32 * j, k1 = (k + 1) & 127;
            a0[j] = s0[k]; b0v[j] = s0[k1];
            a1[j] = s1[k]; b1v[j] = s1[k1];
        }
        sc0 = scale[(size_t)(o0 + r0) * I_ + i0];
        sc1 = scale[(size_t)(o0 + r1) * I_ + i0];
        if (tid < BT) pkr = g_pk8[(size_t)i0 * B_ + b0 + tid];
    }

    for (int it = 0; it < ISEG; it++) {
        const int buf = it & 1;

        // STS phase: pack scaled fp16 pairs (conflict-free STS.32)
        {
            unsigned int* row0 = &sC[buf][r0 * RS];
            unsigned int* row1 = &sC[buf][r1 * RS];
#pragma unroll
            for (int j = 0; j < 4; j++) {
                __half2 p0 = __floats2half2_rn(a0[j] * sc0, b0v[j] * sc0);
                __half2 p1 = __floats2half2_rn(a1[j] * sc1, b1v[j] * sc1);
                row0[lane + 32 * j] = *reinterpret_cast<unsigned int*>(&p0);
                row1[lane + 32 * j] = *reinterpret_cast<unsigned int*>(&p1);
            }
            if (tid < BT) sPk[buf][tid] = pkr;
        }

        // Fetch phase: next iteration's LDGs (latency hidden behind hot loop)
        if (it + 1 < ISEG) {
            const int inx = i0 + it + 1;
            const float* s0 = coeff + ((size_t)(o0 + r0) * I_ + inx) * (size_t)K_;
            const float* s1 = coeff + ((size_t)(o0 + r1) * I_ + inx) * (size_t)K_;
#pragma unroll
            for (int j = 0; j < 4; j++) {
                int k = lane + 32 * j, k1 = (k + 1) & 127;
                a0[j] = s0[k]; b0v[j] = s0[k1];
                a1[j] = s1[k]; b1v[j] = s1[k1];
            }
            sc0 = scale[(size_t)(o0 + r0) * I_ + inx];
            sc1 = scale[(size_t)(o0 + r1) * I_ + inx];
            if (tid < BT) pkr = g_pk8[(size_t)inx * B_ + b0 + tid];
        }

        __syncthreads();  // buffer 'buf' staged; prior buffer's readers all passed last barrier

        // Hot loop, software-pipelined: pk for pair j+1 loads while pair j's gathers+math run.
        const float w = sW[it][lane];
        const char* rowb = (const char*)&sC[buf][lane * RS];
        const uint4* pkp = reinterpret_cast<const uint4*>(&sPk[buf][warp * BPW]);

        uint4 cur4 = pkp[0];
#pragma unroll
        for (int j = 0; j < BPW / 2; j++) {
            uint4 nxt4 = pkp[(j + 1) & (BPW / 2 - 1)];  // j=7 rereads [0]; result unused
            // gathers depend on cur4 (fetched an iteration ago -> issue immediately)
            unsigned int cwA = *(const unsigned int*)(rowb + cur4.y);
            unsigned int cwB = *(const unsigned int*)(rowb + cur4.w);
            float2 afA = __half22float2(*reinterpret_cast<__half2*>(&cur4.x));  // (act, frac)
            float2 afB = __half22float2(*reinterpret_cast<__half2*>(&cur4.z));
            float2 cA  = __half22float2(*reinterpret_cast<__half2*>(&cwA));     // (c_l, c_r)
            float2 cB  = __half22float2(*reinterpret_cast<__half2*>(&cwB));
            float spA = fmaf(afA.y, cA.y - cA.x, cA.x);   // c_l + f*(c_r - c_l)
            float spB = fmaf(afB.y, cB.y - cB.x, cB.x);
            acc[2 * j]     += spA;
            acc[2 * j]      = fmaf(afA.x, w, acc[2 * j]);
            acc[2 * j + 1] += spB;
            acc[2 * j + 1]  = fmaf(afB.x, w, acc[2 * j + 1]);
            cur4 = nxt4;
        }
    }

    // Exclusive partial slice (coalesced 128B rows)
#pragma unroll
    for (int bb = 0; bb < BPW; bb++)
        g_part[blockIdx.z][b0 + warp * BPW + bb][o0 + lane] = acc[bb];
}

__global__ __launch_bounds__(256) void kan_reduce(
    const float* __restrict__ bias, float* __restrict__ out) {
    int t = blockIdx.x * 256 + threadIdx.x;  // one float4 of out each
    int b = t >> 6;
    int oq = t & 63;
    float4 s = reinterpret_cast<const float4*>(&g_part[0][b][0])[oq];
#pragma unroll
    for (int seg = 1; seg < NSEG; seg++) {
        float4 v = reinterpret_cast<const float4*>(&g_part[seg][b][0])[oq];
        s.x += v.x; s.y += v.y; s.z += v.z; s.w += v.w;
    }
    float4 bi = reinterpret_cast<const float4*>(bias)[oq];
    s.x += bi.x; s.y += bi.y; s.z += bi.z; s.w += bi.w;
    reinterpret_cast<float4*>(out)[t] = s;
}

extern "C" void kernel_launch(void* const* d_in, const int* in_sizes, int n_in,
                              void* d_out, int out_size) {
    const float* x     = (const float*)d_in[0];
    const float* bw    = (const float*)d_in[1];
    const float* coeff = (const float*)d_in[2];
    const float* scale = (const float*)d_in[3];
    const float* bias  = (const float*)d_in[4];
    float* out = (float*)d_out;

    prep_kernel<<<(B_ * I_) / 256, 256>>>(x);

    dim3 grid(O_ / OT, B_ / BT, NSEG);  // 8 x 4 x 16 = 512 CTAs
    kan_main<<<grid, 512>>>(bw, coeff, scale);

    kan_reduce<<<(B_ * O_ / 4) / 256, 256>>>(bias, out);
}